// round 10
// baseline (speedup 1.0000x reference)
#include <cuda_runtime.h>
#include <cuda_bf16.h>
#include <math.h>
#include <stdint.h>

#define N_SEQS   2048
#define SEQ_LEN  512
#define N_AA     20
#define M_MI     100
#define N_PAIRS  4950                    // 100*99/2 upper triangle
#define OUT_PSSM 0
#define OUT_CONS (SEQ_LEN * N_AA)        // 10240
#define OUT_MI   (OUT_CONS + SEQ_LEN)    // 10752
#define OUT_TOTAL (OUT_MI + SEQ_LEN * SEQ_LEN)  // 272896

// Scratch (no dynamic allocation allowed)
__device__ unsigned char g_colpack[128 * N_SEQS];    // column-major int8 msa[:, :128] (100 used)
__device__ int           g_part[32][SEQ_LEN][21];    // count partials (plain stores, no zeroing)

// ---------------------------------------------------------------------------
// FUSED PREP: one pass over msa does counts + pack + MI-region zeroing.
// grid (16, 32) x 256 = 512 CTAs (~3.5/SM): CTA covers 32 cols x 64 rows;
// each thread handles 8 rows of one column (coalesced 128B per warp per row).
// Per-warp replica histograms -> plain private smem RMW (no atomics).
// ---------------------------------------------------------------------------
__global__ __launch_bounds__(256) void prep_kernel(const int* __restrict__ msa,
                                                   float* __restrict__ out) {
    __shared__ int cnt[8][32][21];     // [warp][lane(col)][symbol]
    int tid = threadIdx.x, lane = tid & 31, w = tid >> 5;
    for (int v = tid; v < 8 * 32 * 21; v += 256) ((int*)cnt)[v] = 0;

    // Zero MI region: 512*512 floats = 131072 float2 == 512 CTAs * 256 thr
    int gz = (blockIdx.y * 16 + blockIdx.x) * 256 + tid;
    ((float2*)(out + OUT_MI))[gz] = make_float2(0.f, 0.f);
    __syncthreads();

    int col   = blockIdx.x * 32 + lane;
    int rbase = blockIdx.y * 64 + w * 8;
    int* my = cnt[w][lane];

    uint32_t pk0 = 0, pk1 = 0;
#pragma unroll
    for (int s = 0; s < 8; s++) {
        int c = msa[(rbase + s) * SEQ_LEN + col];   // coalesced 128B per warp
        my[c] += 1;                                  // private replica: plain RMW
        if (s < 4) pk0 |= (uint32_t)c << (8 * s);
        else       pk1 |= (uint32_t)c << (8 * (s - 4));
    }
    if (col < M_MI)                                  // pack store, 8B aligned
        *(uint2*)&g_colpack[col * N_SEQS + rbase] = make_uint2(pk0, pk1);
    __syncthreads();

    // Merge 8 replicas -> partial store (no atomics, no pre-zero needed)
    for (int v = tid; v < 32 * 21; v += 256) {
        int l = v / 21, c = v % 21;
        int s = 0;
#pragma unroll
        for (int ww = 0; ww < 8; ww++) s += cnt[ww][l][c];
        g_part[blockIdx.y][blockIdx.x * 32 + l][c] = s;
    }
}

// ---------------------------------------------------------------------------
// PSSM + conservation: one warp per position (lane = amino acid); sums the
// 32 count partials. 64 CTAs x 256.
// ---------------------------------------------------------------------------
__global__ __launch_bounds__(256) void pssm_kernel(float* __restrict__ out, const float* __restrict__ pc) {
    int gtid = blockIdx.x * blockDim.x + threadIdx.x;
    int p = gtid >> 5, lane = gtid & 31;
    if (p >= SEQ_LEN) return;

    int ct = 0;
    if (lane < 20) {
#pragma unroll
        for (int k = 0; k < 32; k++) ct += g_part[k][p][lane];
    }

    int t = ct;
#pragma unroll
    for (int off = 16; off; off >>= 1) t += __shfl_xor_sync(0xffffffffu, t, off);
    int total = t;

    float pcount = 0.01f * pc[0];
    float inv_den = 1.0f / ((float)N_SEQS + pcount * 20.0f);
    float tinv = 1.0f / fmaxf((float)total, 1.0f);

    float ent = 0.0f;
    if (lane < 20) {
        float freq = ((float)ct + pcount) * inv_den;
        out[OUT_PSSM + p * 20 + lane] = logf(freq * 20.0f + 1e-10f);
        float f = (float)ct * tinv;
        ent = -f * log2f(f + 1e-10f);
    }
#pragma unroll
    for (int off = 16; off; off >>= 1) ent += __shfl_xor_sync(0xffffffffu, ent, off);
    if (lane == 0)
        out[OUT_CONS + p] = (total > 0) ? (1.0f - ent * (1.0f / 4.321928094887362f)) : 0.0f;
}

// ---------------------------------------------------------------------------
// MI: one warp per (i<j) pair — measured at the smem-ATOMS floor (14.7us,
// reproduced 4x). 400-bin smem histogram; gap events predicated out.
// Integer log2 LUT epilogue (no MUFU in the hot path). DO NOT TOUCH.
// ---------------------------------------------------------------------------
__global__ __launch_bounds__(256) void mi_kernel(float* __restrict__ mi_out) {
    __shared__ int   hist[8][400];
    __shared__ float lut[2049];       // log2(0..2048)
    __shared__ float slra[8][20];
    __shared__ float slcb[8][20];

    int tid = threadIdx.x, wid = tid >> 5, lane = tid & 31;
    for (int v = tid; v < 2049; v += 256) lut[v] = log2f((float)v);
    __syncthreads();

    int pid = blockIdx.x * 8 + wid;
    if (pid >= N_PAIRS) return;

    // Decode upper-triangle pair index -> (i, j), i < j; T(i) = i*(199-i)/2
    float d = sqrtf(39601.0f - 8.0f * (float)pid);
    int i = (int)((199.0f - d) * 0.5f);
    if (i < 0) i = 0;
    if (i > 98) i = 98;
    while ((((i + 1) * (199 - (i + 1))) >> 1) <= pid) ++i;
    while (((i * (199 - i)) >> 1) > pid) --i;
    int j = pid - ((i * (199 - i)) >> 1) + i + 1;

    int* h = hist[wid];
    for (int v = lane; v < 400; v += 32) h[v] = 0;
    __syncwarp();

    const uint4* ca = (const uint4*)(g_colpack + i * N_SEQS);
    const uint4* cb = (const uint4*)(g_colpack + j * N_SEQS);
#pragma unroll
    for (int it = 0; it < 4; it++) {                // 4 x LDG.128 per operand
        uint4 va = ca[lane + 32 * it];
        uint4 vb = cb[lane + 32 * it];
        const uint32_t wa_[4] = {va.x, va.y, va.z, va.w};
        const uint32_t wb_[4] = {vb.x, vb.y, vb.z, vb.w};
#pragma unroll
        for (int q = 0; q < 4; q++) {
            uint32_t wa = wa_[q], wb = wb_[q];
#pragma unroll
            for (int s = 0; s < 4; s++) {
                int a = (wa >> (8 * s)) & 255;
                int b = (wb >> (8 * s)) & 255;
                if (a < 20 && b < 20)
                    atomicAdd(&h[a * 20 + b], 1);
            }
        }
    }
    __syncwarp();

    // Integer marginals over the 20x20 block
    int rs = 0, cs = 0;
    if (lane < 20) {
#pragma unroll
        for (int b = 0; b < 20; b++) { rs += h[lane * 20 + b]; cs += h[b * 20 + lane]; }
        slra[wid][lane] = lut[rs];
        slcb[wid][lane] = lut[cs];
    }
    int tv = (lane < 20) ? rs : 0;
#pragma unroll
    for (int off = 16; off; off >>= 1) tv += __shfl_xor_sync(0xffffffffu, tv, off);
    int tot = tv;
    __syncwarp();

    int tots = (tot > 0) ? tot : 1;
    float lt = lut[tots];
    float acc = 0.0f;
    for (int c = lane; c < 400; c += 32) {
        int H = h[c];
        if (H > 0) {
            int a = (c * 3277) >> 16;   // c / 20 for c < 400
            int b = c - a * 20;
            acc += (float)H * (lut[H] - slra[wid][a] - slcb[wid][b] + lt);
        }
    }
#pragma unroll
    for (int off = 16; off; off >>= 1) acc += __shfl_xor_sync(0xffffffffu, acc, off);

    if (lane == 0) {
        float mi = (tot > 0) ? acc / (float)tots : 0.0f;
        mi_out[i * SEQ_LEN + j] = mi;
        mi_out[j * SEQ_LEN + i] = mi;
    }
}

// ---------------------------------------------------------------------------
// Launch: SINGLE stream, 3 nodes, no events, no memsets (measured ~zero
// graph overhead for this topology).
// ---------------------------------------------------------------------------
extern "C" void kernel_launch(void* const* d_in, const int* in_sizes, int n_in,
                              void* d_out, int out_size) {
    const int*   msa = (const int*)d_in[0];
    const float* pc  = (const float*)d_in[1];
    float*       out = (float*)d_out;

    prep_kernel<<<dim3(16, 32), 256>>>(msa, out);   // counts + pack + zero MI
    pssm_kernel<<<64, 256>>>(out, pc);              // pssm + conservation
    mi_kernel<<<(N_PAIRS + 7) / 8, 256>>>(out + OUT_MI);  // dominant MI
}

// round 11
// speedup vs baseline: 1.0014x; 1.0014x over previous
#include <cuda_runtime.h>
#include <cuda_bf16.h>
#include <math.h>
#include <stdint.h>

#define N_SEQS   2048
#define SEQ_LEN  512
#define N_AA     20
#define M_MI     100
#define N_PAIRS  4950                    // 100*99/2 upper triangle
#define OUT_PSSM 0
#define OUT_CONS (SEQ_LEN * N_AA)        // 10240
#define OUT_MI   (OUT_CONS + SEQ_LEN)    // 10752
#define OUT_TOTAL (OUT_MI + SEQ_LEN * SEQ_LEN)  // 272896

// Scratch (no dynamic allocation allowed)
__device__ unsigned char g_colpack[128 * N_SEQS];    // column-major int8 msa[:, :128] (100 used)
__device__ int           g_part[16][SEQ_LEN][21];    // count partials (plain stores, no zeroing)

// ---------------------------------------------------------------------------
// FUSED PREP: one pass over msa -> counts + pack + MI-region zeroing.
// grid (16, 16) x 256: CTA covers 32 cols x 128 rows; thread handles 16 rows
// of one column (lane = column -> coalesced 128B per warp per row).
//
// Counting uses FOUR separately-declared byte-counter arrays (rows s -> array
// s&3). Distinct array objects cannot alias -> the compiler keeps 4
// INDEPENDENT 4-deep RMW chains instead of one serialized 16-deep chain
// (critical path ~140 cyc vs ~560). Byte counters: <=4 per chain per thread,
// column total <=128 per CTA -> no overflow. Stride 28 -> bank = 7*lane mod 32
// (conflict-free). Merge via __vadd4 on uint32 groups (byte sums <=128).
// ---------------------------------------------------------------------------
__global__ __launch_bounds__(256) void prep_kernel(const int* __restrict__ msa,
                                                   float* __restrict__ out) {
    __shared__ unsigned char cA[8][32][28];
    __shared__ unsigned char cB[8][32][28];
    __shared__ unsigned char cC[8][32][28];
    __shared__ unsigned char cD[8][32][28];
    int tid = threadIdx.x, lane = tid & 31, w = tid >> 5;

    // Zero counter arrays (7168 bytes each = 1792 words)
    {
        uint32_t* zA = (uint32_t*)cA; uint32_t* zB = (uint32_t*)cB;
        uint32_t* zC = (uint32_t*)cC; uint32_t* zD = (uint32_t*)cD;
        for (int v = tid; v < 1792; v += 256) { zA[v] = 0; zB[v] = 0; zC[v] = 0; zD[v] = 0; }
    }

    // Zero MI region: 512*512 floats = 65536 float4 == 256 CTAs * 256 threads
    int gz = (blockIdx.y * 16 + blockIdx.x) * 256 + tid;
    ((float4*)(out + OUT_MI))[gz] = make_float4(0.f, 0.f, 0.f, 0.f);
    __syncthreads();

    int col   = blockIdx.x * 32 + lane;
    int rbase = blockIdx.y * 128 + w * 16;

    // Load all 16 values first (independent LDGs -> full MLP)
    int vals[16];
#pragma unroll
    for (int s = 0; s < 16; s++)
        vals[s] = msa[(rbase + s) * SEQ_LEN + col];   // coalesced 128B per warp

    // Four independent 4-deep byte RMW chains
#pragma unroll
    for (int s = 0; s < 16; s += 4) {
        cA[w][lane][vals[s + 0]]++;
        cB[w][lane][vals[s + 1]]++;
        cC[w][lane][vals[s + 2]]++;
        cD[w][lane][vals[s + 3]]++;
    }

    // Pack 16 rows -> uint4 (col-major int8) for the MI kernel
    if (col < M_MI) {
        uint32_t pk[4];
#pragma unroll
        for (int g = 0; g < 4; g++)
            pk[g] = (uint32_t)vals[4 * g] | ((uint32_t)vals[4 * g + 1] << 8) |
                    ((uint32_t)vals[4 * g + 2] << 16) | ((uint32_t)vals[4 * g + 3] << 24);
        *(uint4*)&g_colpack[col * N_SEQS + rbase] = make_uint4(pk[0], pk[1], pk[2], pk[3]);
    }
    __syncthreads();

    // Merge: task (l, g) sums 8 warps x 4 arrays of a 4-byte symbol group.
    // Byte-wise totals <= 128 -> __vadd4 safe. 192 tasks, one per thread.
    if (tid < 192) {
        int l = tid / 6, g = tid % 6;           // g covers symbols 4g..4g+3
        uint32_t acc = 0;
#pragma unroll
        for (int ww = 0; ww < 8; ww++) {
            acc = __vadd4(acc, *(const uint32_t*)&cA[ww][l][g * 4]);
            acc = __vadd4(acc, *(const uint32_t*)&cB[ww][l][g * 4]);
            acc = __vadd4(acc, *(const uint32_t*)&cC[ww][l][g * 4]);
            acc = __vadd4(acc, *(const uint32_t*)&cD[ww][l][g * 4]);
        }
        int colg = blockIdx.x * 32 + l;
#pragma unroll
        for (int k = 0; k < 4; k++) {
            int sym = g * 4 + k;
            if (sym < 21)
                g_part[blockIdx.y][colg][sym] = (int)((acc >> (8 * k)) & 0xffu);
        }
    }
}

// ---------------------------------------------------------------------------
// PSSM + conservation: one warp per position (lane = amino acid); sums the
// 16 count partials. 64 CTAs x 256.
// ---------------------------------------------------------------------------
__global__ __launch_bounds__(256) void pssm_kernel(float* __restrict__ out, const float* __restrict__ pc) {
    int gtid = blockIdx.x * blockDim.x + threadIdx.x;
    int p = gtid >> 5, lane = gtid & 31;
    if (p >= SEQ_LEN) return;

    int ct = 0;
    if (lane < 20) {
#pragma unroll
        for (int k = 0; k < 16; k++) ct += g_part[k][p][lane];
    }

    int t = ct;
#pragma unroll
    for (int off = 16; off; off >>= 1) t += __shfl_xor_sync(0xffffffffu, t, off);
    int total = t;

    float pcount = 0.01f * pc[0];
    float inv_den = 1.0f / ((float)N_SEQS + pcount * 20.0f);
    float tinv = 1.0f / fmaxf((float)total, 1.0f);

    float ent = 0.0f;
    if (lane < 20) {
        float freq = ((float)ct + pcount) * inv_den;
        out[OUT_PSSM + p * 20 + lane] = logf(freq * 20.0f + 1e-10f);
        float f = (float)ct * tinv;
        ent = -f * log2f(f + 1e-10f);
    }
#pragma unroll
    for (int off = 16; off; off >>= 1) ent += __shfl_xor_sync(0xffffffffu, ent, off);
    if (lane == 0)
        out[OUT_CONS + p] = (total > 0) ? (1.0f - ent * (1.0f / 4.321928094887362f)) : 0.0f;
}

// ---------------------------------------------------------------------------
// MI: one warp per (i<j) pair — measured at the smem-ATOMS floor (14.7us,
// reproduced 4x). 400-bin smem histogram; gap events predicated out.
// Integer log2 LUT epilogue (no MUFU in the hot path). DO NOT TOUCH.
// ---------------------------------------------------------------------------
__global__ __launch_bounds__(256) void mi_kernel(float* __restrict__ mi_out) {
    __shared__ int   hist[8][400];
    __shared__ float lut[2049];       // log2(0..2048)
    __shared__ float slra[8][20];
    __shared__ float slcb[8][20];

    int tid = threadIdx.x, wid = tid >> 5, lane = tid & 31;
    for (int v = tid; v < 2049; v += 256) lut[v] = log2f((float)v);
    __syncthreads();

    int pid = blockIdx.x * 8 + wid;
    if (pid >= N_PAIRS) return;

    // Decode upper-triangle pair index -> (i, j), i < j; T(i) = i*(199-i)/2
    float d = sqrtf(39601.0f - 8.0f * (float)pid);
    int i = (int)((199.0f - d) * 0.5f);
    if (i < 0) i = 0;
    if (i > 98) i = 98;
    while ((((i + 1) * (199 - (i + 1))) >> 1) <= pid) ++i;
    while (((i * (199 - i)) >> 1) > pid) --i;
    int j = pid - ((i * (199 - i)) >> 1) + i + 1;

    int* h = hist[wid];
    for (int v = lane; v < 400; v += 32) h[v] = 0;
    __syncwarp();

    const uint4* ca = (const uint4*)(g_colpack + i * N_SEQS);
    const uint4* cb = (const uint4*)(g_colpack + j * N_SEQS);
#pragma unroll
    for (int it = 0; it < 4; it++) {                // 4 x LDG.128 per operand
        uint4 va = ca[lane + 32 * it];
        uint4 vb = cb[lane + 32 * it];
        const uint32_t wa_[4] = {va.x, va.y, va.z, va.w};
        const uint32_t wb_[4] = {vb.x, vb.y, vb.z, vb.w};
#pragma unroll
        for (int q = 0; q < 4; q++) {
            uint32_t wa = wa_[q], wb = wb_[q];
#pragma unroll
            for (int s = 0; s < 4; s++) {
                int a = (wa >> (8 * s)) & 255;
                int b = (wb >> (8 * s)) & 255;
                if (a < 20 && b < 20)
                    atomicAdd(&h[a * 20 + b], 1);
            }
        }
    }
    __syncwarp();

    // Integer marginals over the 20x20 block
    int rs = 0, cs = 0;
    if (lane < 20) {
#pragma unroll
        for (int b = 0; b < 20; b++) { rs += h[lane * 20 + b]; cs += h[b * 20 + lane]; }
        slra[wid][lane] = lut[rs];
        slcb[wid][lane] = lut[cs];
    }
    int tv = (lane < 20) ? rs : 0;
#pragma unroll
    for (int off = 16; off; off >>= 1) tv += __shfl_xor_sync(0xffffffffu, tv, off);
    int tot = tv;
    __syncwarp();

    int tots = (tot > 0) ? tot : 1;
    float lt = lut[tots];
    float acc = 0.0f;
    for (int c = lane; c < 400; c += 32) {
        int H = h[c];
        if (H > 0) {
            int a = (c * 3277) >> 16;   // c / 20 for c < 400
            int b = c - a * 20;
            acc += (float)H * (lut[H] - slra[wid][a] - slcb[wid][b] + lt);
        }
    }
#pragma unroll
    for (int off = 16; off; off >>= 1) acc += __shfl_xor_sync(0xffffffffu, acc, off);

    if (lane == 0) {
        float mi = (tot > 0) ? acc / (float)tots : 0.0f;
        mi_out[i * SEQ_LEN + j] = mi;
        mi_out[j * SEQ_LEN + i] = mi;
    }
}

// ---------------------------------------------------------------------------
// Launch: SINGLE stream, 3 nodes, no events, no memsets (measured ~zero
// graph overhead for this topology).
// ---------------------------------------------------------------------------
extern "C" void kernel_launch(void* const* d_in, const int* in_sizes, int n_in,
                              void* d_out, int out_size) {
    const int*   msa = (const int*)d_in[0];
    const float* pc  = (const float*)d_in[1];
    float*       out = (float*)d_out;

    prep_kernel<<<dim3(16, 16), 256>>>(msa, out);   // counts + pack + zero MI
    pssm_kernel<<<64, 256>>>(out, pc);              // pssm + conservation
    mi_kernel<<<(N_PAIRS + 7) / 8, 256>>>(out + OUT_MI);  // dominant MI
}

// round 12
// speedup vs baseline: 1.0144x; 1.0130x over previous
#include <cuda_runtime.h>
#include <cuda_bf16.h>
#include <math.h>
#include <stdint.h>

#define N_SEQS   2048
#define SEQ_LEN  512
#define N_AA     20
#define M_MI     100
#define N_PAIRS  4950                    // 100*99/2 upper triangle
#define OUT_PSSM 0
#define OUT_CONS (SEQ_LEN * N_AA)        // 10240
#define OUT_MI   (OUT_CONS + SEQ_LEN)    // 10752
#define OUT_TOTAL (OUT_MI + SEQ_LEN * SEQ_LEN)  // 272896

#define CNT_CTAS 256                     // count/zero CTAs (blockIdx 0..255)
#define MI_CTAS  619                     // mi CTAs (blockIdx 256..874)
#define MEGA_CTAS (CNT_CTAS + MI_CTAS)   // 875 <= 148*6 -> single wave

// Scratch (no dynamic allocation allowed)
__device__ unsigned char g_colpack[128 * N_SEQS];    // column-major int8 msa[:, :128] (100 used)
__device__ int           g_part[16][SEQ_LEN][21];    // count partials (plain stores, no zeroing)

// ---------------------------------------------------------------------------
// Lean pack: columns 0..99 -> int8 column-major. The ONLY critical-path
// dependency of mi. grid (4, 64) x 256; thread packs 4 rows -> one uint32.
// ---------------------------------------------------------------------------
__global__ __launch_bounds__(256) void pack_kernel(const int* __restrict__ msa) {
    int tid = threadIdx.x, lane = tid & 31, w = tid >> 5;
    int col   = blockIdx.x * 32 + lane;          // 0..127 (stores only col<100)
    int rbase = blockIdx.y * 32 + w * 4;
    uint32_t p0 = 0;
#pragma unroll
    for (int s = 0; s < 4; s++)
        p0 |= (uint32_t)msa[(rbase + s) * SEQ_LEN + col] << (8 * s);
    if (col < M_MI)
        *(uint32_t*)&g_colpack[col * N_SEQS + rbase] = p0;
}

// ---------------------------------------------------------------------------
// MEGA kernel: heterogeneous single-wave grid.
//   CTAs 0..255   : per-position AA counts (R9 measured-good shape) + zero the
//                   COMPLEMENT of mi's write set in the MI output region.
//   CTAs 256..874 : mi, one warp per (i<j) pair — the proven ATOMS-floor code.
// Write sets are disjoint by construction (mi writes exactly the off-diagonal
// of [0:100)^2; count CTAs zero everything else) -> no ordering needed.
// Shared memory is overlaid via a raw byte array (union of both roles, 28KB).
// ---------------------------------------------------------------------------
__global__ __launch_bounds__(256) void mega_kernel(const int* __restrict__ msa,
                                                   float* __restrict__ mi_out) {
    __shared__ __align__(16) unsigned char smem_raw[28672];
    int b = blockIdx.x;
    int tid = threadIdx.x, lane = tid & 31, w = tid >> 5;

    if (b < CNT_CTAS) {
        // ----- COUNT + COMPLEMENT-ZERO branch -----
        int (*cnt)[32][21] = (int(*)[32][21])smem_raw;   // 8*32*21*4 = 21504B
        for (int v = tid; v < 8 * 32 * 21; v += 256) ((int*)cnt)[v] = 0;

        // Zero the complement of mi's write set:
        //   rows 100..511 (all cols): 412*128 = 52736 float4
        //   rows 0..99, cols 100..511: 100*103 = 10300 float4 (col 100 = f4 #25)
        //   diagonal (d,d), d<100: 100 scalars
        int t = b * 256 + tid;
        if (t < 52736) {
            int r = 100 + (t >> 7);
            ((float4*)mi_out)[r * 128 + (t & 127)] = make_float4(0.f, 0.f, 0.f, 0.f);
        } else if (t < 63036) {
            int u = t - 52736;
            int r = u / 103, c4 = 25 + (u - r * 103);
            ((float4*)mi_out)[r * 128 + c4] = make_float4(0.f, 0.f, 0.f, 0.f);
        } else if (t < 63136) {
            int dd = t - 63036;
            mi_out[dd * SEQ_LEN + dd] = 0.f;
        }
        __syncthreads();

        int col   = (b & 15) * 32 + lane;
        int rbase = (b >> 4) * 128 + w * 16;
        int* my = cnt[w][lane];
#pragma unroll
        for (int s = 0; s < 16; s++) {
            int c = msa[(rbase + s) * SEQ_LEN + col];   // coalesced 128B per warp
            my[c] += 1;                                  // private replica: plain RMW
        }
        __syncthreads();

        for (int v = tid; v < 32 * 21; v += 256) {
            int l = v / 21, c = v % 21;
            int s = 0;
#pragma unroll
            for (int ww = 0; ww < 8; ww++) s += cnt[ww][l][c];
            g_part[b >> 4][(b & 15) * 32 + l][c] = s;   // plain store
        }
        return;
    }

    // ----- MI branch (proven ATOMS-floor code; smem via overlay pointers) -----
    int*   hist = (int*)smem_raw;                          // 8*400*4 = 12800
    float* lut  = (float*)(smem_raw + 12800);              // 2049*4  = 8196
    float* slra = (float*)(smem_raw + 12800 + 8196);       // 8*20*4  = 640
    float* slcb = (float*)(smem_raw + 12800 + 8196 + 640); // 8*20*4  = 640

    int wid = w;
    for (int v = tid; v < 2049; v += 256) lut[v] = log2f((float)v);
    __syncthreads();

    int pid = (b - CNT_CTAS) * 8 + wid;
    if (pid >= N_PAIRS) return;

    // Decode upper-triangle pair index -> (i, j), i < j; T(i) = i*(199-i)/2
    float d = sqrtf(39601.0f - 8.0f * (float)pid);
    int i = (int)((199.0f - d) * 0.5f);
    if (i < 0) i = 0;
    if (i > 98) i = 98;
    while ((((i + 1) * (199 - (i + 1))) >> 1) <= pid) ++i;
    while (((i * (199 - i)) >> 1) > pid) --i;
    int j = pid - ((i * (199 - i)) >> 1) + i + 1;

    int* h = hist + wid * 400;
    for (int v = lane; v < 400; v += 32) h[v] = 0;
    __syncwarp();

    const uint4* ca = (const uint4*)(g_colpack + i * N_SEQS);
    const uint4* cb = (const uint4*)(g_colpack + j * N_SEQS);
#pragma unroll
    for (int it = 0; it < 4; it++) {                // 4 x LDG.128 per operand
        uint4 va = ca[lane + 32 * it];
        uint4 vb = cb[lane + 32 * it];
        const uint32_t wa_[4] = {va.x, va.y, va.z, va.w};
        const uint32_t wb_[4] = {vb.x, vb.y, vb.z, vb.w};
#pragma unroll
        for (int q = 0; q < 4; q++) {
            uint32_t wa = wa_[q], wb = wb_[q];
#pragma unroll
            for (int s = 0; s < 4; s++) {
                int a = (wa >> (8 * s)) & 255;
                int bb = (wb >> (8 * s)) & 255;
                if (a < 20 && bb < 20)
                    atomicAdd(&h[a * 20 + bb], 1);
            }
        }
    }
    __syncwarp();

    // Integer marginals over the 20x20 block
    int rs = 0, cs = 0;
    if (lane < 20) {
#pragma unroll
        for (int bq = 0; bq < 20; bq++) { rs += h[lane * 20 + bq]; cs += h[bq * 20 + lane]; }
        slra[wid * 20 + lane] = lut[rs];
        slcb[wid * 20 + lane] = lut[cs];
    }
    int tv = (lane < 20) ? rs : 0;
#pragma unroll
    for (int off = 16; off; off >>= 1) tv += __shfl_xor_sync(0xffffffffu, tv, off);
    int tot = tv;
    __syncwarp();

    int tots = (tot > 0) ? tot : 1;
    float lt = lut[tots];
    float acc = 0.0f;
    for (int c = lane; c < 400; c += 32) {
        int H = h[c];
        if (H > 0) {
            int a = (c * 3277) >> 16;   // c / 20 for c < 400
            int bq = c - a * 20;
            acc += (float)H * (lut[H] - slra[wid * 20 + a] - slcb[wid * 20 + bq] + lt);
        }
    }
#pragma unroll
    for (int off = 16; off; off >>= 1) acc += __shfl_xor_sync(0xffffffffu, acc, off);

    if (lane == 0) {
        float mi = (tot > 0) ? acc / (float)tots : 0.0f;
        mi_out[i * SEQ_LEN + j] = mi;
        mi_out[j * SEQ_LEN + i] = mi;
    }
}

// ---------------------------------------------------------------------------
// PSSM + conservation: one warp per position (lane = amino acid); sums the
// 16 count partials. 64 CTAs x 256.
// ---------------------------------------------------------------------------
__global__ __launch_bounds__(256) void pssm_kernel(float* __restrict__ out, const float* __restrict__ pc) {
    int gtid = blockIdx.x * blockDim.x + threadIdx.x;
    int p = gtid >> 5, lane = gtid & 31;
    if (p >= SEQ_LEN) return;

    int ct = 0;
    if (lane < 20) {
#pragma unroll
        for (int k = 0; k < 16; k++) ct += g_part[k][p][lane];
    }

    int t = ct;
#pragma unroll
    for (int off = 16; off; off >>= 1) t += __shfl_xor_sync(0xffffffffu, t, off);
    int total = t;

    float pcount = 0.01f * pc[0];
    float inv_den = 1.0f / ((float)N_SEQS + pcount * 20.0f);
    float tinv = 1.0f / fmaxf((float)total, 1.0f);

    float ent = 0.0f;
    if (lane < 20) {
        float freq = ((float)ct + pcount) * inv_den;
        out[OUT_PSSM + p * 20 + lane] = logf(freq * 20.0f + 1e-10f);
        float f = (float)ct * tinv;
        ent = -f * log2f(f + 1e-10f);
    }
#pragma unroll
    for (int off = 16; off; off >>= 1) ent += __shfl_xor_sync(0xffffffffu, ent, off);
    if (lane == 0)
        out[OUT_CONS + p] = (total > 0) ? (1.0f - ent * (1.0f / 4.321928094887362f)) : 0.0f;
}

// ---------------------------------------------------------------------------
// Launch: SINGLE stream, 3 nodes. Overlap of count under mi happens INSIDE
// mega_kernel (heterogeneous CTAs, single wave) -> no event overhead.
// ---------------------------------------------------------------------------
extern "C" void kernel_launch(void* const* d_in, const int* in_sizes, int n_in,
                              void* d_out, int out_size) {
    const int*   msa = (const int*)d_in[0];
    const float* pc  = (const float*)d_in[1];
    float*       out = (float*)d_out;

    pack_kernel<<<dim3(4, 64), 256>>>(msa);               // mi's only dependency
    mega_kernel<<<MEGA_CTAS, 256>>>(msa, out + OUT_MI);   // mi + count + zero, one wave
    pssm_kernel<<<64, 256>>>(out, pc);                    // pssm + conservation
}